// round 13
// baseline (speedup 1.0000x reference)
#include <cuda_runtime.h>

#define NMAX 100000
#define HID 256
#define EMB 128

#define QS 65535.0f
#define QI 1.5259021896696422e-05f   // 1/65535

// ---------------- scratch (static device globals; no allocation) -------------
__device__ int            g_degc[NMAX];            // in-degree COUNT (deg = c+1)
__device__ unsigned short g_disq[NMAX];            // dis quantized to u16 (scale 65535)
__device__ unsigned int   g_tq[NMAX];              // integer sum of quantized dis[src]
__device__ float          g_thr[HID];              // sorted relu breakpoints
__device__ int            g_sidx[HID];             // permutation: sorted pos -> h
__device__ __align__(16) float2 g_tab[(HID + 1) * EMB]; // per-interval (A, C)

// ---- per-block edge dtype detection (reads first 32B of src half, cached) ---
__device__ __forceinline__ int edges_is32(const void* edges) {
    const unsigned long long* p = (const unsigned long long*)edges;
    unsigned long long x = p[0] | p[1] | p[2] | p[3];
    return (unsigned int)(x >> 32) != 0u;  // hi words nonzero => packed int32 pairs
}

// ---- K0: zero g_degc (4 nodes/thread, int4 stores) ---------------------------
__global__ void k_zero(int N) {
    int n = (blockIdx.x * blockDim.x + threadIdx.x) * 4;
    if (n >= N) return;
    if (n + 4 <= N) {
        *(int4*)&g_degc[n] = make_int4(0, 0, 0, 0);
    } else {
        for (int m = n; m < N; m++) g_degc[m] = 0;
    }
}

// ---- K1: degree atomics over dst (4 e/t); LAST block sorts breakpoints ------
// The sort block hides under the ~20us atomic pass; its g_thr/g_sidx are
// consumed two launches later (tab blocks inside k_scat).
__global__ void __launch_bounds__(256, 8) k_deg(const void* __restrict__ edges, int E,
                                                const float* __restrict__ W1,
                                                const float* __restrict__ b1) {
    if (blockIdx.x == gridDim.x - 1) {
        int t = threadIdx.x;
        __shared__ float key[HID];
        __shared__ int   idx[HID];
        // relu(s*w+b) crossing for s>0: thr=-b/w if (w>0,b<0) or (w<0,b>0)
        float w = W1[t], b = b1[t];
        float thr = 3.0e38f;
        if ((w > 0.f && b < 0.f) || (w < 0.f && b > 0.f)) thr = -b / w;
        key[t] = thr; idx[t] = t;
        __syncthreads();
        for (int k = 2; k <= HID; k <<= 1) {
            for (int j = k >> 1; j > 0; j >>= 1) {
                int p = t ^ j;
                if (p > t) {
                    bool up = ((t & k) == 0);
                    float ka = key[t], kb = key[p];
                    if ((ka > kb) == up) {
                        key[t] = kb; key[p] = ka;
                        int ia = idx[t]; idx[t] = idx[p]; idx[p] = ia;
                    }
                }
                __syncthreads();
            }
        }
        g_thr[t] = key[t];
        g_sidx[t] = idx[t];
        return;
    }

    int is32 = edges_is32(edges);
    int i = (blockIdx.x * blockDim.x + threadIdx.x) * 4;
    if (i >= E) return;
    if (is32) {
        const int* p = (const int*)edges + E;  // dst half
        if (i + 4 <= E) {
            int4 v = __ldg((const int4*)(p + i));
            atomicAdd(&g_degc[v.x], 1); atomicAdd(&g_degc[v.y], 1);
            atomicAdd(&g_degc[v.z], 1); atomicAdd(&g_degc[v.w], 1);
        } else {
            for (int j = i; j < E; j++) atomicAdd(&g_degc[p[j]], 1);
        }
    } else {
        const long long* p = (const long long*)edges + E;
        if (i + 4 <= E) {
            const int4* q = (const int4*)(p + i);
            int4 a = __ldg(q), b = __ldg(q + 1);
            atomicAdd(&g_degc[a.x], 1); atomicAdd(&g_degc[a.z], 1);
            atomicAdd(&g_degc[b.x], 1); atomicAdd(&g_degc[b.z], 1);
        } else {
            for (int j = i; j < E; j++) atomicAdd(&g_degc[(int)p[j]], 1);
        }
    }
}

// ---- K2: quantize dis to u16 AND zero g_tq (4 nodes/thread) -----------------
__global__ void k_dis(int N) {
    int n = (blockIdx.x * blockDim.x + threadIdx.x) * 4;
    if (n >= N) return;
    if (n + 4 <= N) {
        int4 c = *(const int4*)&g_degc[n];
        unsigned int q0 = __float2uint_rn(rsqrtf((float)(c.x + 1)) * QS);
        unsigned int q1 = __float2uint_rn(rsqrtf((float)(c.y + 1)) * QS);
        unsigned int q2 = __float2uint_rn(rsqrtf((float)(c.z + 1)) * QS);
        unsigned int q3 = __float2uint_rn(rsqrtf((float)(c.w + 1)) * QS);
        *(uint2*)&g_disq[n] = make_uint2(q0 | (q1 << 16), q2 | (q3 << 16));
        *(uint4*)&g_tq[n] = make_uint4(0u, 0u, 0u, 0u);
    } else {
        for (int m = n; m < N; m++) {
            g_disq[m] = (unsigned short)__float2uint_rn(rsqrtf((float)(g_degc[m] + 1)) * QS);
            g_tq[m] = 0u;
        }
    }
}

// ---- K3 union: blocks [0,EMB) build tables (FIRST, so they run in wave 1 and
//      hide under the atomic pass); blocks [EMB, +scatBlocks) do the scatter. -
__device__ __forceinline__ void scat1(int src, int dst) {
    unsigned int q = (unsigned int)__ldg(&g_disq[src]);
    atomicAdd(&g_tq[dst], q);
}
__global__ void __launch_bounds__(256, 8) k_scat(const void* __restrict__ edges, int E,
                                                 const float* __restrict__ W1,
                                                 const float* __restrict__ b1,
                                                 const float* __restrict__ W2,
                                                 const float* __restrict__ b2) {
    if (blockIdx.x < EMB) {
        // ---- table-build block (column j): base + delta prefix-scan ---------
        __shared__ float sa[HID], sc[HID];  // deltas -> scan
        __shared__ float ra[HID], rc[HID];  // base terms -> reduction
        int j = blockIdx.x;
        int t = threadIdx.x;

        float w = W1[t], b = b1[t];
        float w2 = __ldg(&W2[t * EMB + j]);
        bool act = (b > 0.f) || (b == 0.f && w > 0.f);
        ra[t] = act ? w * w2 : 0.f;
        rc[t] = act ? b * w2 : 0.f;

        // delta at sorted position t (toggled term is exactly 0 at its
        // breakpoint => interval boundary handling is value-exact)
        int h = g_sidx[t];
        float wh = W1[h], bh = b1[h];
        float w2h = __ldg(&W2[h * EMB + j]);
        float d = (wh > 0.f && bh < 0.f) ? 1.f : ((wh < 0.f && bh > 0.f) ? -1.f : 0.f);
        sa[t] = d * wh * w2h;
        sc[t] = d * bh * w2h;
        __syncthreads();

        #pragma unroll
        for (int s = HID / 2; s > 0; s >>= 1) {
            if (t < s) { ra[t] += ra[t + s]; rc[t] += rc[t + s]; }
            __syncthreads();
        }
        float A0 = ra[0];
        float C0 = rc[0] + b2[j];

        #pragma unroll
        for (int off = 1; off < HID; off <<= 1) {
            float va = 0.f, vc = 0.f;
            if (t >= off) { va = sa[t - off]; vc = sc[t - off]; }
            __syncthreads();
            if (t >= off) { sa[t] += va; sc[t] += vc; }
            __syncthreads();
        }

        if (t == 0) g_tab[j] = make_float2(A0, C0);
        g_tab[(t + 1) * EMB + j] = make_float2(A0 + sa[t], C0 + sc[t]);
        return;
    }

    int is32 = edges_is32(edges);
    int i = ((blockIdx.x - EMB) * blockDim.x + threadIdx.x) * 4;
    if (i >= E) return;
    if (is32) {
        const int* ps = (const int*)edges;
        const int* pd = ps + E;
        if (i + 4 <= E) {
            int4 s = __ldcs((const int4*)(ps + i));
            int4 d = __ldg((const int4*)(pd + i));
            scat1(s.x, d.x); scat1(s.y, d.y); scat1(s.z, d.z); scat1(s.w, d.w);
        } else {
            for (int j = i; j < E; j++) scat1(ps[j], pd[j]);
        }
    } else {
        const long long* ps = (const long long*)edges;
        const long long* pd = ps + E;
        if (i + 4 <= E) {
            const int4* qs = (const int4*)(ps + i);
            const int4* qd = (const int4*)(pd + i);
            int4 s0 = __ldcs(qs), s1 = __ldcs(qs + 1);
            int4 d0 = __ldg(qd),  d1 = __ldg(qd + 1);
            scat1(s0.x, d0.x); scat1(s0.z, d0.z);
            scat1(s1.x, d1.x); scat1(s1.z, d1.z);
        } else {
            for (int j = i; j < E; j++) scat1((int)ps[j], (int)pd[j]);
        }
    }
}

// ---- K4: output. grid (nodeBlocks, 4): each thread 2 nodes x 32 columns -----
__global__ void k_out(float* __restrict__ out, int N) {
    __shared__ float sthr[HID];
    for (int i = threadIdx.x; i < HID; i += blockDim.x) sthr[i] = g_thr[i];
    __syncthreads();

    int n0 = (blockIdx.x * blockDim.x + threadIdx.x) * 2;
    if (n0 >= N) return;
    int jbase = blockIdx.y * (EMB / 4);   // 32 columns per y-slice
    bool has2 = (n0 + 1 < N) && ((N & 1) == 0);
    int n1 = has2 ? n0 + 1 : n0;

    float d0 = rsqrtf((float)(g_degc[n0] + 1));
    float d1 = rsqrtf((float)(g_degc[n1] + 1));
    float s0 = d0 * ((float)g_tq[n0] * QI + d0);
    float s1 = d1 * ((float)g_tq[n1] * QI + d1);

    int lo0 = 0, hi0 = HID, lo1 = 0, hi1 = HID;
    #pragma unroll
    for (int it = 0; it < 8; it++) {
        int m0 = (lo0 + hi0) >> 1;
        if (sthr[m0] < s0) lo0 = m0 + 1; else hi0 = m0;
        int m1 = (lo1 + hi1) >> 1;
        if (sthr[m1] < s1) lo1 = m1 + 1; else hi1 = m1;
    }

    const float4* __restrict__ r0 = (const float4*)(g_tab + lo0 * EMB + jbase);
    const float4* __restrict__ r1 = (const float4*)(g_tab + lo1 * EMB + jbase);

    if (has2) {
        #pragma unroll
        for (int jj = 0; jj < EMB / 8; jj++) {       // 16 iters x 2 columns
            float4 va = __ldg(&r0[jj]);
            float4 vb = __ldg(&r1[jj]);
            float xa0 = fmaf(s0, va.x, va.y), xa1 = fmaf(s0, va.z, va.w);
            float xb0 = fmaf(s1, vb.x, vb.y), xb1 = fmaf(s1, vb.z, vb.w);
            float ya0 = __fdividef(1.f, 1.f + __expf(-xa0));
            float ya1 = __fdividef(1.f, 1.f + __expf(-xa1));
            float yb0 = __fdividef(1.f, 1.f + __expf(-xb0));
            float yb1 = __fdividef(1.f, 1.f + __expf(-xb1));
            int j = jbase + jj * 2;
            *(float2*)&out[j * N + n0]       = make_float2(ya0, yb0);
            *(float2*)&out[(j + 1) * N + n0] = make_float2(ya1, yb1);
        }
    } else {
        #pragma unroll
        for (int jj = 0; jj < EMB / 8; jj++) {
            float4 va = __ldg(&r0[jj]);
            float xa0 = fmaf(s0, va.x, va.y), xa1 = fmaf(s0, va.z, va.w);
            int j = jbase + jj * 2;
            out[j * N + n0]       = __fdividef(1.f, 1.f + __expf(-xa0));
            out[(j + 1) * N + n0] = __fdividef(1.f, 1.f + __expf(-xa1));
        }
    }
}

// ---------------- launch (pure kernel launches; no host API calls) ------------
extern "C" void kernel_launch(void* const* d_in, const int* in_sizes, int n_in,
                              void* d_out, int out_size) {
    const void*  edges = d_in[0];
    const float* W1    = (const float*)d_in[1];
    const float* b1    = (const float*)d_in[2];
    const float* W2    = (const float*)d_in[3];
    const float* b2    = (const float*)d_in[4];
    int E = in_sizes[0] / 2;
    int N = out_size / EMB;
    if (N > NMAX) N = NMAX;

    const int TB = 256;
    int gZ = (N + TB * 4 - 1) / (TB * 4);
    int gE = (E + TB * 4 - 1) / (TB * 4);
    int gD = (N + TB * 4 - 1) / (TB * 4);
    int gO = (N + TB * 2 - 1) / (TB * 2);

    k_zero<<<gZ, TB>>>(N);
    k_deg <<<gE + 1, TB>>>(edges, E, W1, b1);
    k_dis <<<gD, TB>>>(N);
    k_scat<<<EMB + gE, TB>>>(edges, E, W1, b1, W2, b2);
    k_out <<<dim3(gO, 4), TB>>>((float*)d_out, N);
}

// round 14
// speedup vs baseline: 1.0300x; 1.0300x over previous
#include <cuda_runtime.h>

#define NMAX 100000
#define HID 256
#define EMB 128

#define QS 65535.0f
#define QI 1.5259021896696422e-05f   // 1/65535

// ---------------- scratch (static device globals; no allocation) -------------
// Invariant: g_degc and g_tq are ZERO on entry to kernel_launch (static init on
// first call; re-zeroed by k_distab on every call after their last use window).
__device__ int            g_degc[NMAX];            // in-degree COUNT (deg = c+1)
__device__ unsigned short g_disq[NMAX];            // dis quantized to u16 (scale 65535)
__device__ float          g_disf[NMAX];            // dis full precision (for k_out)
__device__ unsigned int   g_tq[NMAX];              // integer sum of quantized dis[src]
__device__ float          g_thr[HID];              // sorted relu breakpoints
__device__ int            g_sidx[HID];             // permutation: sorted pos -> h
__device__ __align__(16) float2 g_tab[(HID + 1) * EMB]; // per-interval (A, C)

// ---- per-block edge dtype detection (reads first 32B of src half, cached) ---
__device__ __forceinline__ int edges_is32(const void* edges) {
    const unsigned long long* p = (const unsigned long long*)edges;
    unsigned long long x = p[0] | p[1] | p[2] | p[3];
    return (unsigned int)(x >> 32) != 0u;  // hi words nonzero => packed int32 pairs
}

// ---- K1: degree atomics over dst (4 e/t); LAST block sorts breakpoints ------
// g_degc is zero on entry (see invariant above). The sort block hides under
// the ~20us atomic pass; g_thr/g_sidx are consumed next launch (tab blocks).
__global__ void __launch_bounds__(256, 8) k_deg(const void* __restrict__ edges, int E,
                                                const float* __restrict__ W1,
                                                const float* __restrict__ b1) {
    if (blockIdx.x == gridDim.x - 1) {
        int t = threadIdx.x;
        __shared__ float key[HID];
        __shared__ int   idx[HID];
        // relu(s*w+b) crossing for s>0: thr=-b/w if (w>0,b<0) or (w<0,b>0)
        float w = W1[t], b = b1[t];
        float thr = 3.0e38f;
        if ((w > 0.f && b < 0.f) || (w < 0.f && b > 0.f)) thr = -b / w;
        key[t] = thr; idx[t] = t;
        __syncthreads();
        for (int k = 2; k <= HID; k <<= 1) {
            for (int j = k >> 1; j > 0; j >>= 1) {
                int p = t ^ j;
                if (p > t) {
                    bool up = ((t & k) == 0);
                    float ka = key[t], kb = key[p];
                    if ((ka > kb) == up) {
                        key[t] = kb; key[p] = ka;
                        int ia = idx[t]; idx[t] = idx[p]; idx[p] = ia;
                    }
                }
                __syncthreads();
            }
        }
        g_thr[t] = key[t];
        g_sidx[t] = idx[t];
        return;
    }

    int is32 = edges_is32(edges);
    int i = (blockIdx.x * blockDim.x + threadIdx.x) * 4;
    if (i >= E) return;
    if (is32) {
        const int* p = (const int*)edges + E;  // dst half
        if (i + 4 <= E) {
            int4 v = __ldg((const int4*)(p + i));
            atomicAdd(&g_degc[v.x], 1); atomicAdd(&g_degc[v.y], 1);
            atomicAdd(&g_degc[v.z], 1); atomicAdd(&g_degc[v.w], 1);
        } else {
            for (int j = i; j < E; j++) atomicAdd(&g_degc[p[j]], 1);
        }
    } else {
        const long long* p = (const long long*)edges + E;
        if (i + 4 <= E) {
            const int4* q = (const int4*)(p + i);
            int4 a = __ldg(q), b = __ldg(q + 1);
            atomicAdd(&g_degc[a.x], 1); atomicAdd(&g_degc[a.z], 1);
            atomicAdd(&g_degc[b.x], 1); atomicAdd(&g_degc[b.z], 1);
        } else {
            for (int j = i; j < E; j++) atomicAdd(&g_degc[(int)p[j]], 1);
        }
    }
}

// ---- K2 union: blocks [0,disBlocks): read degc -> write disq (u16) + disf
//      (f32); then zero degc and tq for the next replay (degc is dead after
//      this kernel — k_out reads disf instead). Remaining EMB blocks build the
//      per-interval tables; both halves fit in one wave and overlap. ----------
__global__ void k_distab(int N, int disBlocks,
                         const float* __restrict__ W1, const float* __restrict__ b1,
                         const float* __restrict__ W2, const float* __restrict__ b2) {
    if (blockIdx.x < disBlocks) {
        int n = (blockIdx.x * blockDim.x + threadIdx.x) * 4;
        if (n >= N) return;
        if (n + 4 <= N) {
            int4 c = *(const int4*)&g_degc[n];
            float f0 = rsqrtf((float)(c.x + 1));
            float f1 = rsqrtf((float)(c.y + 1));
            float f2 = rsqrtf((float)(c.z + 1));
            float f3 = rsqrtf((float)(c.w + 1));
            unsigned int q0 = __float2uint_rn(f0 * QS);
            unsigned int q1 = __float2uint_rn(f1 * QS);
            unsigned int q2 = __float2uint_rn(f2 * QS);
            unsigned int q3 = __float2uint_rn(f3 * QS);
            *(uint2*)&g_disq[n] = make_uint2(q0 | (q1 << 16), q2 | (q3 << 16));
            *(float4*)&g_disf[n] = make_float4(f0, f1, f2, f3);
            *(int4*)&g_degc[n] = make_int4(0, 0, 0, 0);      // self-clean
            *(uint4*)&g_tq[n]  = make_uint4(0u, 0u, 0u, 0u); // zero before scat
        } else {
            for (int m = n; m < N; m++) {
                float f = rsqrtf((float)(g_degc[m] + 1));
                g_disq[m] = (unsigned short)__float2uint_rn(f * QS);
                g_disf[m] = f;
                g_degc[m] = 0;
                g_tq[m] = 0u;
            }
        }
        return;
    }

    // ---- table-build block (column j): base + delta prefix-scan -------------
    __shared__ float sa[HID], sc[HID];  // deltas -> scan
    __shared__ float ra[HID], rc[HID];  // base terms -> reduction
    int j = blockIdx.x - disBlocks;
    int t = threadIdx.x;
    if (t >= HID) return;

    float w = W1[t], b = b1[t];
    float w2 = __ldg(&W2[t * EMB + j]);
    bool act = (b > 0.f) || (b == 0.f && w > 0.f);
    ra[t] = act ? w * w2 : 0.f;
    rc[t] = act ? b * w2 : 0.f;

    // delta at sorted position t (toggled term is exactly 0 at its breakpoint
    // => interval boundary handling is value-exact)
    int h = g_sidx[t];
    float wh = W1[h], bh = b1[h];
    float w2h = __ldg(&W2[h * EMB + j]);
    float d = (wh > 0.f && bh < 0.f) ? 1.f : ((wh < 0.f && bh > 0.f) ? -1.f : 0.f);
    sa[t] = d * wh * w2h;
    sc[t] = d * bh * w2h;
    __syncthreads();

    #pragma unroll
    for (int s = HID / 2; s > 0; s >>= 1) {
        if (t < s) { ra[t] += ra[t + s]; rc[t] += rc[t + s]; }
        __syncthreads();
    }
    float A0 = ra[0];
    float C0 = rc[0] + b2[j];

    #pragma unroll
    for (int off = 1; off < HID; off <<= 1) {
        float va = 0.f, vc = 0.f;
        if (t >= off) { va = sa[t - off]; vc = sc[t - off]; }
        __syncthreads();
        if (t >= off) { sa[t] += va; sc[t] += vc; }
        __syncthreads();
    }

    if (t == 0) g_tab[j] = make_float2(A0, C0);
    g_tab[(t + 1) * EMB + j] = make_float2(A0 + sa[t], C0 + sc[t]);
}

// ---- K3: tq[dst] += disq[src]  (u16 L1 gather + u32 L2 atomic) --------------
__device__ __forceinline__ void scat1(int src, int dst) {
    unsigned int q = (unsigned int)__ldg(&g_disq[src]);
    atomicAdd(&g_tq[dst], q);
}
__global__ void __launch_bounds__(256, 8) k_scat(const void* __restrict__ edges, int E) {
    int is32 = edges_is32(edges);
    int i = (blockIdx.x * blockDim.x + threadIdx.x) * 4;
    if (i >= E) return;
    if (is32) {
        const int* ps = (const int*)edges;
        const int* pd = ps + E;
        if (i + 4 <= E) {
            int4 s = __ldcs((const int4*)(ps + i));
            int4 d = __ldg((const int4*)(pd + i));
            scat1(s.x, d.x); scat1(s.y, d.y); scat1(s.z, d.z); scat1(s.w, d.w);
        } else {
            for (int j = i; j < E; j++) scat1(ps[j], pd[j]);
        }
    } else {
        const long long* ps = (const long long*)edges;
        const long long* pd = ps + E;
        if (i + 4 <= E) {
            const int4* qs = (const int4*)(ps + i);
            const int4* qd = (const int4*)(pd + i);
            int4 s0 = __ldcs(qs), s1 = __ldcs(qs + 1);
            int4 d0 = __ldg(qd),  d1 = __ldg(qd + 1);
            scat1(s0.x, d0.x); scat1(s0.z, d0.z);
            scat1(s1.x, d1.x); scat1(s1.z, d1.z);
        } else {
            for (int j = i; j < E; j++) scat1((int)ps[j], (int)pd[j]);
        }
    }
}

// ---- K4: output. grid (nodeBlocks, 4): each thread 2 nodes x 32 columns -----
__global__ void k_out(float* __restrict__ out, int N) {
    __shared__ float sthr[HID];
    for (int i = threadIdx.x; i < HID; i += blockDim.x) sthr[i] = g_thr[i];
    __syncthreads();

    int n0 = (blockIdx.x * blockDim.x + threadIdx.x) * 2;
    if (n0 >= N) return;
    int jbase = blockIdx.y * (EMB / 4);   // 32 columns per y-slice
    bool has2 = (n0 + 1 < N) && ((N & 1) == 0);
    int n1 = has2 ? n0 + 1 : n0;

    float d0 = g_disf[n0];
    float d1 = g_disf[n1];
    float s0 = d0 * ((float)g_tq[n0] * QI + d0);
    float s1 = d1 * ((float)g_tq[n1] * QI + d1);

    int lo0 = 0, hi0 = HID, lo1 = 0, hi1 = HID;
    #pragma unroll
    for (int it = 0; it < 8; it++) {
        int m0 = (lo0 + hi0) >> 1;
        if (sthr[m0] < s0) lo0 = m0 + 1; else hi0 = m0;
        int m1 = (lo1 + hi1) >> 1;
        if (sthr[m1] < s1) lo1 = m1 + 1; else hi1 = m1;
    }

    const float4* __restrict__ r0 = (const float4*)(g_tab + lo0 * EMB + jbase);
    const float4* __restrict__ r1 = (const float4*)(g_tab + lo1 * EMB + jbase);

    if (has2) {
        #pragma unroll
        for (int jj = 0; jj < EMB / 8; jj++) {       // 16 iters x 2 columns
            float4 va = __ldg(&r0[jj]);
            float4 vb = __ldg(&r1[jj]);
            float xa0 = fmaf(s0, va.x, va.y), xa1 = fmaf(s0, va.z, va.w);
            float xb0 = fmaf(s1, vb.x, vb.y), xb1 = fmaf(s1, vb.z, vb.w);
            float ya0 = __fdividef(1.f, 1.f + __expf(-xa0));
            float ya1 = __fdividef(1.f, 1.f + __expf(-xa1));
            float yb0 = __fdividef(1.f, 1.f + __expf(-xb0));
            float yb1 = __fdividef(1.f, 1.f + __expf(-xb1));
            int j = jbase + jj * 2;
            *(float2*)&out[j * N + n0]       = make_float2(ya0, yb0);
            *(float2*)&out[(j + 1) * N + n0] = make_float2(ya1, yb1);
        }
    } else {
        #pragma unroll
        for (int jj = 0; jj < EMB / 8; jj++) {
            float4 va = __ldg(&r0[jj]);
            float xa0 = fmaf(s0, va.x, va.y), xa1 = fmaf(s0, va.z, va.w);
            int j = jbase + jj * 2;
            out[j * N + n0]       = __fdividef(1.f, 1.f + __expf(-xa0));
            out[(j + 1) * N + n0] = __fdividef(1.f, 1.f + __expf(-xa1));
        }
    }
}

// ---------------- launch (pure kernel launches; no host API calls) ------------
extern "C" void kernel_launch(void* const* d_in, const int* in_sizes, int n_in,
                              void* d_out, int out_size) {
    const void*  edges = d_in[0];
    const float* W1    = (const float*)d_in[1];
    const float* b1    = (const float*)d_in[2];
    const float* W2    = (const float*)d_in[3];
    const float* b2    = (const float*)d_in[4];
    int E = in_sizes[0] / 2;
    int N = out_size / EMB;
    if (N > NMAX) N = NMAX;

    const int TB = 256;
    int gE = (E + TB * 4 - 1) / (TB * 4);
    int gD = (N + TB * 4 - 1) / (TB * 4);
    int gO = (N + TB * 2 - 1) / (TB * 2);

    k_deg   <<<gE + 1, TB>>>(edges, E, W1, b1);
    k_distab<<<gD + EMB, TB>>>(N, gD, W1, b1, W2, b2);
    k_scat  <<<gE, TB>>>(edges, E);
    k_out   <<<dim3(gO, 4), TB>>>((float*)d_out, N);
}